// round 9
// baseline (speedup 1.0000x reference)
#include <cuda_runtime.h>
#include <cuda_fp16.h>
#include <stdint.h>

#define NN   4096
#define EE   65536
#define OC   200
#define KPAD 256    // padded K span for GEMM2 fills
#define NCAT 512    // padded N for GEMM1 weight concat

// ---------------------------------------------------------------------------
// Scratch (device globals; no runtime allocation allowed)
// ---------------------------------------------------------------------------
__device__ __align__(16) __half g_w1[NCAT * NN];          // [n,k] = Wcat[k,n]
__device__ __align__(16) float g_h[NN * OC];
__device__ __align__(16) float g_z[NN * OC];
__device__ __align__(16) __half g_wd[NN * KPAD];          // [n,k] = W_dec[k,n], padded

// ---------------------------------------------------------------------------
// PTX helpers
// ---------------------------------------------------------------------------
__device__ __forceinline__ uint32_t smem_u32(const void* p) {
    uint32_t a;
    asm("{ .reg .u64 t; cvta.to.shared.u64 t, %1; cvt.u32.u64 %0, t; }" : "=r"(a) : "l"(p));
    return a;
}
#define CP16(sa, gp)  asm volatile("cp.async.cg.shared.global [%0], [%1], 16;" :: "r"(sa), "l"(gp))
#define CP_COMMIT()   asm volatile("cp.async.commit_group;" ::: "memory")
#define CP_WAIT(n)    asm volatile("cp.async.wait_group %0;" :: "n"(n) : "memory")

__device__ __forceinline__ void ldsm_x4(uint32_t* r, uint32_t addr) {
    asm volatile("ldmatrix.sync.aligned.m8n8.x4.shared.b16 {%0,%1,%2,%3}, [%4];"
                 : "=r"(r[0]), "=r"(r[1]), "=r"(r[2]), "=r"(r[3]) : "r"(addr));
}
__device__ __forceinline__ void ldsm_x2(uint32_t* r, uint32_t addr) {
    asm volatile("ldmatrix.sync.aligned.m8n8.x2.shared.b16 {%0,%1}, [%2];"
                 : "=r"(r[0]), "=r"(r[1]) : "r"(addr));
}
__device__ __forceinline__ void mma16816(float* d, const uint32_t* a, const uint32_t* b) {
    asm volatile("mma.sync.aligned.m16n8k16.row.col.f32.f16.f16.f32 "
                 "{%0,%1,%2,%3}, {%4,%5,%6,%7}, {%8,%9}, {%0,%1,%2,%3};"
                 : "+f"(d[0]), "+f"(d[1]), "+f"(d[2]), "+f"(d[3])
                 : "r"(a[0]), "r"(a[1]), "r"(a[2]), "r"(a[3]), "r"(b[0]), "r"(b[1]));
}

// SW128-style swizzle for 128-byte rows
__device__ __forceinline__ uint32_t tile_addr(uint32_t base, int row, int kbyte) {
    uint32_t off = row * 128 + kbyte;
    return base + (off ^ ((off >> 3) & 0x70));
}

// SMEM: 3 stages x (A 64x64 fp16 = 8KB, B 128x64 = 16KB) = 24KB/stage
#define OFF_A      0
#define OFF_B      8192
#define BUF_B      24576
#define NSTAGE     3
#define SMEM_TOTAL (NSTAGE * BUF_B)      // 73728; 2 CTAs/SM -> 147KB

// Fill one ROWS x 64-col fp16 tile from fp16 source via cp.async (B side).
template<int ROWS>
__device__ __forceinline__ void fill_tile(uint32_t sbase, const __half* __restrict__ gsrc,
                                          int row0, int stride, int k0) {
    const int tid = threadIdx.x;
    #pragma unroll
    for (int t = 0; t < ROWS / 32; t++) {
        const int q = tid + t * 256;
        const int r = q >> 3;
        const int c16 = q & 7;
        uint32_t off = r * 128 + c16 * 16;
        uint32_t sw = off ^ ((off >> 3) & 0x70);
        const void* gp = gsrc + (size_t)(row0 + r) * stride + k0 + c16 * 8;
        CP16(sbase + sw, gp);
    }
}

// Fill one 64x64 fp16 A-tile by converting from fp32 source (synchronous
// LDG -> cvt -> STS).  RELUMASK: apply relu and zero 8-col chunks >= OC.
template<bool RELUMASK>
__device__ __forceinline__ void fill_a_cvt(char* smem, int stage_off,
                                           const float* __restrict__ src,
                                           int row0, int stride, int k0) {
    const int tid = threadIdx.x;
    #pragma unroll
    for (int t = 0; t < 2; t++) {
        const int q = tid + t * 256;          // 0..511: 64 rows x 8 chunks
        const int r = q >> 3;
        const int c16 = q & 7;
        uint32_t off = r * 128 + c16 * 16;
        uint32_t sw = off ^ ((off >> 3) & 0x70);
        uint4 pk;
        const int col0 = k0 + c16 * 8;
        if (RELUMASK && col0 >= OC) {
            pk = make_uint4(0u, 0u, 0u, 0u);
        } else {
            const float* gp = src + (size_t)(row0 + r) * stride + col0;
            float4 v0 = *reinterpret_cast<const float4*>(gp);
            float4 v1 = *reinterpret_cast<const float4*>(gp + 4);
            if (RELUMASK) {
                v0.x = fmaxf(v0.x, 0.f); v0.y = fmaxf(v0.y, 0.f);
                v0.z = fmaxf(v0.z, 0.f); v0.w = fmaxf(v0.w, 0.f);
                v1.x = fmaxf(v1.x, 0.f); v1.y = fmaxf(v1.y, 0.f);
                v1.z = fmaxf(v1.z, 0.f); v1.w = fmaxf(v1.w, 0.f);
            }
            __half2 h0 = __floats2half2_rn(v0.x, v0.y);
            __half2 h1 = __floats2half2_rn(v0.z, v0.w);
            __half2 h2 = __floats2half2_rn(v1.x, v1.y);
            __half2 h3 = __floats2half2_rn(v1.z, v1.w);
            pk.x = *reinterpret_cast<uint32_t*>(&h0);
            pk.y = *reinterpret_cast<uint32_t*>(&h1);
            pk.z = *reinterpret_cast<uint32_t*>(&h2);
            pk.w = *reinterpret_cast<uint32_t*>(&h3);
        }
        *reinterpret_cast<uint4*>(smem + stage_off + sw) = pk;
    }
}

// ---------------------------------------------------------------------------
// Preprocessing: weights only (fp32 -> fp16, transposed)
//   blocks [0, 8192)     : W_rel|W_root -> g_w1
//   blocks [8192, 12288) : W_dec -> g_wd
// ---------------------------------------------------------------------------
__global__ __launch_bounds__(256) void conv_pre_kernel(
    const float* __restrict__ W_rel, const float* __restrict__ W_root,
    const float* __restrict__ W_dec)
{
    const int bid = blockIdx.x;
    if (bid < 8192) {
        const int idx = bid * 256 + threadIdx.x;             // n*4096 + k, n<512
        const int n = idx >> 12, k = idx & 4095;
        float v = 0.f;
        if (n < OC)          v = W_rel[k * OC + n];
        else if (n < 2 * OC) v = W_root[k * OC + (n - OC)];
        g_w1[idx] = __float2half(v);
    } else {
        const int idx = (bid - 8192) * 256 + threadIdx.x;    // n*256 + k
        const int n = idx >> 8, k = idx & 255;
        float v = (k < OC) ? W_dec[(size_t)k * NN + n] : 0.f;
        g_wd[idx] = __float2half(v);
    }
}

// ---------------------------------------------------------------------------
// Edge scatter: g_z[dst] += g_h[src] * w
// ---------------------------------------------------------------------------
__global__ __launch_bounds__(256) void scatter_kernel(const int* __restrict__ ei,
                                                      const float* __restrict__ ew) {
    const int warp = (blockIdx.x * 256 + threadIdx.x) >> 5;
    const int lane = threadIdx.x & 31;
    if (warp >= EE) return;
    const int src = ei[warp];
    const int dst = ei[EE + warp];
    const float w = ew[warp];
    const float4* hs = reinterpret_cast<const float4*>(&g_h[src * OC]);
    float4* zd = reinterpret_cast<float4*>(&g_z[dst * OC]);
    #pragma unroll 2
    for (int c = lane; c < OC / 4; c += 32) {
        const float4 v = __ldg(hs + c);
        asm volatile("red.global.add.v4.f32 [%0], {%1, %2, %3, %4};"
                     :: "l"(zd + c), "f"(v.x * w), "f"(v.y * w), "f"(v.z * w), "f"(v.w * w)
                     : "memory");
    }
}

// ---------------------------------------------------------------------------
// mma.sync mainloop: 64x128 CTA tile, BK=64, 8 warps (2 row x 4 col),
// warp tile 32x32 (mi=2); plain fp16 MMA; 3-stage pipeline.
// A converted on the fly from fp32 (sync STS); B via cp.async.
// ---------------------------------------------------------------------------
template<int NITER, int LAST_KS, bool RELUMASK>
__device__ __forceinline__ void mma_mainloop(float acc[2][4][4], char* smem, uint32_t sb,
    const float* A32, int arow0, int astride,
    const __half* B, int brow0, int bstride)
{
    const int wid = threadIdx.x >> 5;
    const int lane = threadIdx.x & 31;
    const int wrbase = (wid >> 2) * 32;   // warp row base (0 or 32)
    const int wcbase = (wid & 3) * 32;    // warp col base (0,32,64,96)

    const int a_row = wrbase + (lane & 15);
    const int a_kb  = (lane >> 4) * 16;
    const int b_row = wcbase + (lane & 7);
    const int b_kb  = ((lane >> 3) & 1) * 16;

    // prologue: fill stages 0 and 1 (A sync-converted, B async)
    fill_a_cvt<RELUMASK>(smem, 0 * BUF_B + OFF_A, A32, arow0, astride, 0);
    fill_tile<128>(sb + 0 * BUF_B + OFF_B, B, brow0, bstride, 0);
    CP_COMMIT();
    fill_a_cvt<RELUMASK>(smem, 1 * BUF_B + OFF_A, A32, arow0, astride, 64);
    fill_tile<128>(sb + 1 * BUF_B + OFF_B, B, brow0, bstride, 64);
    CP_COMMIT();

    int st = 0;
    int fill_st = 2;
    #pragma unroll 1
    for (int iter = 0; iter < NITER; ++iter) {
        CP_WAIT(1);            // B of stage `st` complete (2 groups pending at entry)
        __syncthreads();       // A STS visible; stage `fill_st` fully consumed

        if (iter + 2 < NITER) {
            fill_a_cvt<RELUMASK>(smem, fill_st * BUF_B + OFF_A, A32, arow0, astride,
                                 (iter + 2) * 64);
            fill_tile<128>(sb + fill_st * BUF_B + OFF_B, B, brow0, bstride, (iter + 2) * 64);
        }
        CP_COMMIT();           // always commit (possibly empty) to keep the count exact

        const uint32_t tA = sb + st * BUF_B + OFF_A;
        const uint32_t tB = sb + st * BUF_B + OFF_B;
        const int nks = (iter == NITER - 1) ? LAST_KS : 4;

        #pragma unroll
        for (int ks = 0; ks < 4; ks++) {
            if (ks >= nks) break;
            uint32_t a[2][4], b[4][2];
            #pragma unroll
            for (int mi = 0; mi < 2; mi++)
                ldsm_x4(a[mi], tile_addr(tA, a_row + mi * 16, ks * 32 + a_kb));
            #pragma unroll
            for (int ni = 0; ni < 4; ni++)
                ldsm_x2(b[ni], tile_addr(tB, b_row + ni * 8, ks * 32 + b_kb));
            #pragma unroll
            for (int mi = 0; mi < 2; mi++)
                #pragma unroll
                for (int ni = 0; ni < 4; ni++)
                    mma16816(acc[mi][ni], a[mi], b[ni]);
        }
        st = (st == NSTAGE - 1) ? 0 : st + 1;
        fill_st = (fill_st == NSTAGE - 1) ? 0 : fill_st + 1;
    }
}

// ---------------------------------------------------------------------------
// GEMM1: [g_h | g_z] (4096 x 400) = x @ [W_rel | W_root]    grid (4, 64)
// A = x fp32 (converted in-fill).
// ---------------------------------------------------------------------------
__global__ __launch_bounds__(256, 2) void gemm1_mma(const float* __restrict__ x,
                                                    const float* __restrict__ b_rel) {
    extern __shared__ __align__(1024) char smem[];
    const uint32_t sb = smem_u32(smem);
    const int rowBase = blockIdx.y * 64;
    const int colBase = blockIdx.x * 128;

    float acc[2][4][4];
    #pragma unroll
    for (int i = 0; i < 2; i++)
        #pragma unroll
        for (int j = 0; j < 4; j++)
            #pragma unroll
            for (int t = 0; t < 4; t++) acc[i][j][t] = 0.f;

    mma_mainloop<NN / 64, 4, false>(acc, smem, sb, x, rowBase, NN, g_w1, colBase, NN);

    const int wid = threadIdx.x >> 5, lane = threadIdx.x & 31;
    const int wrbase = (wid >> 2) * 32, wcbase = (wid & 3) * 32;
    #pragma unroll
    for (int mi = 0; mi < 2; mi++) {
        #pragma unroll
        for (int ni = 0; ni < 4; ni++) {
            const int r0 = rowBase + wrbase + mi * 16 + (lane >> 2);
            const int gc = colBase + wcbase + ni * 8 + (lane & 3) * 2;
            #pragma unroll
            for (int h = 0; h < 2; h++) {
                const int r = r0 + h * 8;
                const float v0 = acc[mi][ni][h * 2 + 0];
                const float v1 = acc[mi][ni][h * 2 + 1];
                if (gc < OC) {
                    g_h[r * OC + gc] = v0;
                    g_h[r * OC + gc + 1] = v1;
                } else if (gc < 2 * OC) {
                    const int c = gc - OC;
                    g_z[r * OC + c] = v0 + __ldg(&b_rel[c]);
                    if (c + 1 < OC) g_z[r * OC + c + 1] = v1 + __ldg(&b_rel[c + 1]);
                }
            }
        }
    }
}

// ---------------------------------------------------------------------------
// GEMM2: out (4096 x 4096) = relu(z) @ W_dec + b_dec    grid (32, 64)
// A = g_z fp32 (relu+convert in-fill, chunk-masked at OC).
// Effective K = 208 (13 k16-steps): niter=4, last iteration 1 step.
// ---------------------------------------------------------------------------
__global__ __launch_bounds__(256, 2) void gemm2_mma(const float* __restrict__ b_dec,
                                                    float* __restrict__ out) {
    extern __shared__ __align__(1024) char smem[];
    const uint32_t sb = smem_u32(smem);
    const int rowBase = blockIdx.y * 64;
    const int colBase = blockIdx.x * 128;

    float acc[2][4][4];
    #pragma unroll
    for (int i = 0; i < 2; i++)
        #pragma unroll
        for (int j = 0; j < 4; j++)
            #pragma unroll
            for (int t = 0; t < 4; t++) acc[i][j][t] = 0.f;

    mma_mainloop<4, 1, true>(acc, smem, sb, g_z, rowBase, OC, g_wd, colBase, KPAD);

    const int wid = threadIdx.x >> 5, lane = threadIdx.x & 31;
    const int wrbase = (wid >> 2) * 32, wcbase = (wid & 3) * 32;
    #pragma unroll
    for (int mi = 0; mi < 2; mi++) {
        #pragma unroll
        for (int ni = 0; ni < 4; ni++) {
            const int r0 = rowBase + wrbase + mi * 16 + (lane >> 2);
            const int gc = colBase + wcbase + ni * 8 + (lane & 3) * 2;
            const float b0 = __ldg(&b_dec[gc]);
            const float b1 = __ldg(&b_dec[gc + 1]);
            #pragma unroll
            for (int h = 0; h < 2; h++) {
                const int r = r0 + h * 8;
                float2 o;
                o.x = acc[mi][ni][h * 2 + 0] + b0;
                o.y = acc[mi][ni][h * 2 + 1] + b1;
                *reinterpret_cast<float2*>(&out[(size_t)r * NN + gc]) = o;
            }
        }
    }
}

// ---------------------------------------------------------------------------
// Launch.  Inputs: x, edge_index, edge_weight, W_rel, b_rel, W_root, W_dec, b_dec
// ---------------------------------------------------------------------------
extern "C" void kernel_launch(void* const* d_in, const int* in_sizes, int n_in,
                              void* d_out, int out_size) {
    const float* x      = (const float*)d_in[0];
    const int*   ei     = (const int*)  d_in[1];
    const float* ew     = (const float*)d_in[2];
    const float* W_rel  = (const float*)d_in[3];
    const float* b_rel  = (const float*)d_in[4];
    const float* W_root = (const float*)d_in[5];
    const float* W_dec  = (const float*)d_in[6];
    const float* b_dec  = (const float*)d_in[7];
    float* out = (float*)d_out;

    cudaFuncSetAttribute(gemm1_mma, cudaFuncAttributeMaxDynamicSharedMemorySize, SMEM_TOTAL);
    cudaFuncSetAttribute(gemm2_mma, cudaFuncAttributeMaxDynamicSharedMemorySize, SMEM_TOTAL);

    conv_pre_kernel<<<12288, 256>>>(W_rel, W_root, W_dec);

    gemm1_mma<<<dim3(4, 64), 256, SMEM_TOTAL>>>(x, b_rel);
    scatter_kernel<<<8192, 256>>>(ei, ew);
    gemm2_mma<<<dim3(32, 64), 256, SMEM_TOTAL>>>(b_dec, out);
}

// round 11
// speedup vs baseline: 1.1721x; 1.1721x over previous
#include <cuda_runtime.h>
#include <cuda_fp16.h>
#include <stdint.h>

#define NN   4096
#define EE   65536
#define OC   200
#define KPAD 256    // padded K for GEMM2
#define NCAT 512    // padded N for GEMM1 weight concat

// ---------------------------------------------------------------------------
// Scratch (device globals; no runtime allocation allowed)
// ---------------------------------------------------------------------------
__device__ __align__(16) __half g_xh[(size_t)NN * NN];    // x as fp16, 32 MB
__device__ __align__(16) __half g_w1[NCAT * NN];          // [n,k] = Wcat[k,n]
__device__ __align__(16) float g_h[NN * OC];
__device__ __align__(16) float g_z[NN * OC];
__device__ __align__(16) __half g_zh[NN * KPAD];          // relu(z) as fp16, K-padded
__device__ __align__(16) __half g_wd[NN * KPAD];          // [n,k] = W_dec[k,n], padded

// ---------------------------------------------------------------------------
// PTX helpers
// ---------------------------------------------------------------------------
__device__ __forceinline__ uint32_t smem_u32(const void* p) {
    uint32_t a;
    asm("{ .reg .u64 t; cvta.to.shared.u64 t, %1; cvt.u32.u64 %0, t; }" : "=r"(a) : "l"(p));
    return a;
}
#define CP16(sa, gp)  asm volatile("cp.async.cg.shared.global [%0], [%1], 16;" :: "r"(sa), "l"(gp))
#define CP_COMMIT()   asm volatile("cp.async.commit_group;" ::: "memory")
#define CP_WAIT(n)    asm volatile("cp.async.wait_group %0;" :: "n"(n) : "memory")

__device__ __forceinline__ void ldsm_x4(uint32_t* r, uint32_t addr) {
    asm volatile("ldmatrix.sync.aligned.m8n8.x4.shared.b16 {%0,%1,%2,%3}, [%4];"
                 : "=r"(r[0]), "=r"(r[1]), "=r"(r[2]), "=r"(r[3]) : "r"(addr));
}
__device__ __forceinline__ void ldsm_x2(uint32_t* r, uint32_t addr) {
    asm volatile("ldmatrix.sync.aligned.m8n8.x2.shared.b16 {%0,%1}, [%2];"
                 : "=r"(r[0]), "=r"(r[1]) : "r"(addr));
}
__device__ __forceinline__ void mma16816(float* d, const uint32_t* a, const uint32_t* b) {
    asm volatile("mma.sync.aligned.m16n8k16.row.col.f32.f16.f16.f32 "
                 "{%0,%1,%2,%3}, {%4,%5,%6,%7}, {%8,%9}, {%0,%1,%2,%3};"
                 : "+f"(d[0]), "+f"(d[1]), "+f"(d[2]), "+f"(d[3])
                 : "r"(a[0]), "r"(a[1]), "r"(a[2]), "r"(a[3]), "r"(b[0]), "r"(b[1]));
}

// SW128-style swizzle for 128-byte rows
__device__ __forceinline__ uint32_t tile_addr(uint32_t base, int row, int kbyte) {
    uint32_t off = row * 128 + kbyte;
    return base + (off ^ ((off >> 3) & 0x70));
}

// SMEM: 4 stages x (A 64x64 fp16 = 8KB, B 128x64 = 16KB) = 24KB/stage
#define OFF_A      0
#define OFF_B      8192
#define BUF_B      24576
#define NSTAGE     4
#define SMEM_TOTAL (NSTAGE * BUF_B)      // 98304; 2 CTAs/SM -> 192KB

// Fill one ROWS x 64-col fp16 tile (swizzled), 256 threads.
template<int ROWS>
__device__ __forceinline__ void fill_tile(uint32_t sbase, const __half* __restrict__ gsrc,
                                          int row0, int stride, int k0) {
    const int tid = threadIdx.x;
    #pragma unroll
    for (int t = 0; t < ROWS / 32; t++) {            // ROWS*8 chunks / 256 threads
        const int q = tid + t * 256;
        const int r = q >> 3;
        const int c16 = q & 7;
        uint32_t off = r * 128 + c16 * 16;
        uint32_t sw = off ^ ((off >> 3) & 0x70);
        const void* gp = gsrc + (size_t)(row0 + r) * stride + k0 + c16 * 8;
        CP16(sbase + sw, gp);
    }
}

__device__ __forceinline__ void fill_stage(uint32_t sbase, int k0,
    const __half* A, int arow0, int astride,
    const __half* B, int brow0, int bstride)
{
    fill_tile<64>(sbase + OFF_A, A, arow0, astride, k0);
    fill_tile<128>(sbase + OFF_B, B, brow0, bstride, k0);
}

// ---------------------------------------------------------------------------
// Preprocessing: fp32 -> fp16 (single rounding)
// ---------------------------------------------------------------------------
__global__ __launch_bounds__(256) void conv_pre_kernel(
    const float* __restrict__ x,
    const float* __restrict__ W_rel, const float* __restrict__ W_root,
    const float* __restrict__ W_dec)
{
    const int bid = blockIdx.x;
    if (bid < 16384) {
        const size_t i = ((size_t)bid * 256 + threadIdx.x) * 4;
        float4 v = *reinterpret_cast<const float4*>(x + i);
        *reinterpret_cast<__half2*>(g_xh + i)     = __half2(__float2half(v.x), __float2half(v.y));
        *reinterpret_cast<__half2*>(g_xh + i + 2) = __half2(__float2half(v.z), __float2half(v.w));
    } else if (bid < 24576) {
        const int idx = (bid - 16384) * 256 + threadIdx.x;   // n*4096 + k, n<512
        const int n = idx >> 12, k = idx & 4095;
        float v = 0.f;
        if (n < OC)          v = W_rel[k * OC + n];
        else if (n < 2 * OC) v = W_root[k * OC + (n - OC)];
        g_w1[idx] = __float2half(v);
    } else {
        const int idx = (bid - 24576) * 256 + threadIdx.x;   // n*256 + k
        const int n = idx >> 8, k = idx & 255;
        float v = (k < OC) ? W_dec[(size_t)k * NN + n] : 0.f;
        g_wd[idx] = __float2half(v);
    }
}

// relu(z) -> fp16, 8 elems/thread; only cols < 208 consumed by gemm2.
__global__ __launch_bounds__(256) void conv_z_kernel() {
    const int idx = blockIdx.x * 256 + threadIdx.x;
    const int m = idx >> 5;
    const int kk = (idx & 31) * 8;
    if (kk >= 208) return;
    __half2 h[4];
    if (kk < OC) {
        const float4 v0 = *reinterpret_cast<const float4*>(&g_z[m * OC + kk]);
        const float4 v1 = *reinterpret_cast<const float4*>(&g_z[m * OC + kk + 4]);
        h[0] = __half2(__float2half(fmaxf(v0.x, 0.f)), __float2half(fmaxf(v0.y, 0.f)));
        h[1] = __half2(__float2half(fmaxf(v0.z, 0.f)), __float2half(fmaxf(v0.w, 0.f)));
        h[2] = __half2(__float2half(fmaxf(v1.x, 0.f)), __float2half(fmaxf(v1.y, 0.f)));
        h[3] = __half2(__float2half(fmaxf(v1.z, 0.f)), __float2half(fmaxf(v1.w, 0.f)));
    } else {
        #pragma unroll
        for (int t = 0; t < 4; t++) h[t] = __half2(__float2half(0.f), __float2half(0.f));
    }
    #pragma unroll
    for (int t = 0; t < 4; t++)
        *reinterpret_cast<__half2*>(g_zh + m * KPAD + kk + 2 * t) = h[t];
}

// ---------------------------------------------------------------------------
// Edge scatter: g_z[dst] += g_h[src] * w
// ---------------------------------------------------------------------------
__global__ __launch_bounds__(256) void scatter_kernel(const int* __restrict__ ei,
                                                      const float* __restrict__ ew) {
    const int warp = (blockIdx.x * 256 + threadIdx.x) >> 5;
    const int lane = threadIdx.x & 31;
    if (warp >= EE) return;
    const int src = ei[warp];
    const int dst = ei[EE + warp];
    const float w = ew[warp];
    const float4* hs = reinterpret_cast<const float4*>(&g_h[src * OC]);
    float4* zd = reinterpret_cast<float4*>(&g_z[dst * OC]);
    #pragma unroll 2
    for (int c = lane; c < OC / 4; c += 32) {
        const float4 v = __ldg(hs + c);
        asm volatile("red.global.add.v4.f32 [%0], {%1, %2, %3, %4};"
                     :: "l"(zd + c), "f"(v.x * w), "f"(v.y * w), "f"(v.z * w), "f"(v.w * w)
                     : "memory");
    }
}

// ---------------------------------------------------------------------------
// mma.sync mainloop: 64x128 CTA tile, BK=64, 8 warps (2 row x 4 col),
// warp tile 32x32 (mi=2); plain fp16 MMA; 4-stage cp.async pipeline
// (3 prologue fills, prefetch distance 3).
// ---------------------------------------------------------------------------
template<int NITER, int LAST_KS>
__device__ __forceinline__ void mma_mainloop(float acc[2][4][4], uint32_t sb,
    const __half* A, int arow0, int astride,
    const __half* B, int brow0, int bstride)
{
    const int wid = threadIdx.x >> 5;
    const int lane = threadIdx.x & 31;
    const int wrbase = (wid >> 2) * 32;   // warp row base (0 or 32)
    const int wcbase = (wid & 3) * 32;    // warp col base (0,32,64,96)

    const int a_row = wrbase + (lane & 15);
    const int a_kb  = (lane >> 4) * 16;
    const int b_row = wcbase + (lane & 7);
    const int b_kb  = ((lane >> 3) & 1) * 16;

    // prologue: fill stages 0..2 (NITER >= 3 for both call sites: 64 and 4)
    fill_stage(sb + 0 * BUF_B, 0,   A, arow0, astride, B, brow0, bstride);
    CP_COMMIT();
    fill_stage(sb + 1 * BUF_B, 64,  A, arow0, astride, B, brow0, bstride);
    CP_COMMIT();
    fill_stage(sb + 2 * BUF_B, 128, A, arow0, astride, B, brow0, bstride);
    CP_COMMIT();

    #pragma unroll 1
    for (int iter = 0; iter < NITER; ++iter) {
        const int st = iter & 3;
        CP_WAIT(2);            // stage `st` complete (exactly 3 groups pending at entry)
        __syncthreads();       // all warps done reading the stage the next fill overwrites

        if (iter + 3 < NITER)
            fill_stage(sb + ((iter + 3) & 3) * BUF_B, (iter + 3) * 64,
                       A, arow0, astride, B, brow0, bstride);
        CP_COMMIT();           // always commit (possibly empty) to keep the count exact

        const uint32_t tA = sb + st * BUF_B + OFF_A;
        const uint32_t tB = sb + st * BUF_B + OFF_B;
        const int nks = (iter == NITER - 1) ? LAST_KS : 4;

        #pragma unroll
        for (int ks = 0; ks < 4; ks++) {
            if (ks >= nks) break;
            uint32_t a[2][4], b[4][2];
            #pragma unroll
            for (int mi = 0; mi < 2; mi++)
                ldsm_x4(a[mi], tile_addr(tA, a_row + mi * 16, ks * 32 + a_kb));
            #pragma unroll
            for (int ni = 0; ni < 4; ni++)
                ldsm_x2(b[ni], tile_addr(tB, b_row + ni * 8, ks * 32 + b_kb));
            #pragma unroll
            for (int mi = 0; mi < 2; mi++)
                #pragma unroll
                for (int ni = 0; ni < 4; ni++)
                    mma16816(acc[mi][ni], a[mi], b[ni]);
        }
    }
}

// ---------------------------------------------------------------------------
// GEMM1: [g_h | g_z] (4096 x 400) = x @ [W_rel | W_root]    grid (4, 64)
// ---------------------------------------------------------------------------
__global__ __launch_bounds__(256, 2) void gemm1_mma(const float* __restrict__ b_rel) {
    extern __shared__ __align__(1024) char smem[];
    const uint32_t sb = smem_u32(smem);
    const int rowBase = blockIdx.y * 64;
    const int colBase = blockIdx.x * 128;

    float acc[2][4][4];
    #pragma unroll
    for (int i = 0; i < 2; i++)
        #pragma unroll
        for (int j = 0; j < 4; j++)
            #pragma unroll
            for (int t = 0; t < 4; t++) acc[i][j][t] = 0.f;

    mma_mainloop<NN / 64, 4>(acc, sb, g_xh, rowBase, NN, g_w1, colBase, NN);

    const int wid = threadIdx.x >> 5, lane = threadIdx.x & 31;
    const int wrbase = (wid >> 2) * 32, wcbase = (wid & 3) * 32;
    #pragma unroll
    for (int mi = 0; mi < 2; mi++) {
        #pragma unroll
        for (int ni = 0; ni < 4; ni++) {
            const int r0 = rowBase + wrbase + mi * 16 + (lane >> 2);
            const int gc = colBase + wcbase + ni * 8 + (lane & 3) * 2;
            #pragma unroll
            for (int h = 0; h < 2; h++) {
                const int r = r0 + h * 8;
                const float v0 = acc[mi][ni][h * 2 + 0];
                const float v1 = acc[mi][ni][h * 2 + 1];
                if (gc < OC) {
                    g_h[r * OC + gc] = v0;
                    g_h[r * OC + gc + 1] = v1;
                } else if (gc < 2 * OC) {
                    const int c = gc - OC;
                    g_z[r * OC + c] = v0 + __ldg(&b_rel[c]);
                    if (c + 1 < OC) g_z[r * OC + c + 1] = v1 + __ldg(&b_rel[c + 1]);
                }
            }
        }
    }
}

// ---------------------------------------------------------------------------
// GEMM2: out (4096 x 4096) = relu(z) @ W_dec + b_dec    grid (32, 64)
// Effective K = 208 (13 k16-steps): niter=4, last iteration 1 step.
// ---------------------------------------------------------------------------
__global__ __launch_bounds__(256, 2) void gemm2_mma(const float* __restrict__ b_dec,
                                                    float* __restrict__ out) {
    extern __shared__ __align__(1024) char smem[];
    const uint32_t sb = smem_u32(smem);
    const int rowBase = blockIdx.y * 64;
    const int colBase = blockIdx.x * 128;

    float acc[2][4][4];
    #pragma unroll
    for (int i = 0; i < 2; i++)
        #pragma unroll
        for (int j = 0; j < 4; j++)
            #pragma unroll
            for (int t = 0; t < 4; t++) acc[i][j][t] = 0.f;

    mma_mainloop<4, 1>(acc, sb, g_zh, rowBase, KPAD, g_wd, colBase, KPAD);

    const int wid = threadIdx.x >> 5, lane = threadIdx.x & 31;
    const int wrbase = (wid >> 2) * 32, wcbase = (wid & 3) * 32;
    #pragma unroll
    for (int mi = 0; mi < 2; mi++) {
        #pragma unroll
        for (int ni = 0; ni < 4; ni++) {
            const int r0 = rowBase + wrbase + mi * 16 + (lane >> 2);
            const int gc = colBase + wcbase + ni * 8 + (lane & 3) * 2;
            const float b0 = __ldg(&b_dec[gc]);
            const float b1 = __ldg(&b_dec[gc + 1]);
            #pragma unroll
            for (int h = 0; h < 2; h++) {
                const int r = r0 + h * 8;
                float2 o;
                o.x = acc[mi][ni][h * 2 + 0] + b0;
                o.y = acc[mi][ni][h * 2 + 1] + b1;
                *reinterpret_cast<float2*>(&out[(size_t)r * NN + gc]) = o;
            }
        }
    }
}

// ---------------------------------------------------------------------------
// Launch.  Inputs: x, edge_index, edge_weight, W_rel, b_rel, W_root, W_dec, b_dec
// ---------------------------------------------------------------------------
extern "C" void kernel_launch(void* const* d_in, const int* in_sizes, int n_in,
                              void* d_out, int out_size) {
    const float* x      = (const float*)d_in[0];
    const int*   ei     = (const int*)  d_in[1];
    const float* ew     = (const float*)d_in[2];
    const float* W_rel  = (const float*)d_in[3];
    const float* b_rel  = (const float*)d_in[4];
    const float* W_root = (const float*)d_in[5];
    const float* W_dec  = (const float*)d_in[6];
    const float* b_dec  = (const float*)d_in[7];
    float* out = (float*)d_out;

    cudaFuncSetAttribute(gemm1_mma, cudaFuncAttributeMaxDynamicSharedMemorySize, SMEM_TOTAL);
    cudaFuncSetAttribute(gemm2_mma, cudaFuncAttributeMaxDynamicSharedMemorySize, SMEM_TOTAL);

    conv_pre_kernel<<<28672, 256>>>(x, W_rel, W_root, W_dec);

    gemm1_mma<<<dim3(4, 64), 256, SMEM_TOTAL>>>(b_rel);
    scatter_kernel<<<8192, 256>>>(ei, ew);
    conv_z_kernel<<<512, 256>>>();
    gemm2_mma<<<dim3(32, 64), 256, SMEM_TOTAL>>>(b_dec, out);
}

// round 12
// speedup vs baseline: 1.2206x; 1.0414x over previous
#include <cuda_runtime.h>
#include <cuda_fp16.h>
#include <stdint.h>

#define NN   4096
#define EE   65536
#define OC   200
#define KPAD 256    // padded K for GEMM2
#define NCAT 512    // padded N for GEMM1 weight concat

// ---------------------------------------------------------------------------
// Scratch (device globals; no runtime allocation allowed)
// ---------------------------------------------------------------------------
__device__ __align__(16) __half g_w1[NCAT * NN];          // [n,k] = Wcat[k,n]
__device__ __align__(16) float g_h[NN * OC];
__device__ __align__(16) float g_z[NN * OC];
__device__ __align__(16) __half g_zh[NN * KPAD];          // relu(z) as fp16, K-padded
__device__ __align__(16) __half g_wd[NN * KPAD];          // [n,k] = W_dec[k,n], padded

// ---------------------------------------------------------------------------
// PTX helpers
// ---------------------------------------------------------------------------
__device__ __forceinline__ uint32_t smem_u32(const void* p) {
    uint32_t a;
    asm("{ .reg .u64 t; cvta.to.shared.u64 t, %1; cvt.u32.u64 %0, t; }" : "=r"(a) : "l"(p));
    return a;
}
#define CP16(sa, gp)  asm volatile("cp.async.cg.shared.global [%0], [%1], 16;" :: "r"(sa), "l"(gp))
#define CP_COMMIT()   asm volatile("cp.async.commit_group;" ::: "memory")
#define CP_WAIT(n)    asm volatile("cp.async.wait_group %0;" :: "n"(n) : "memory")

__device__ __forceinline__ void ldsm_x4(uint32_t* r, uint32_t addr) {
    asm volatile("ldmatrix.sync.aligned.m8n8.x4.shared.b16 {%0,%1,%2,%3}, [%4];"
                 : "=r"(r[0]), "=r"(r[1]), "=r"(r[2]), "=r"(r[3]) : "r"(addr));
}
__device__ __forceinline__ void ldsm_x2(uint32_t* r, uint32_t addr) {
    asm volatile("ldmatrix.sync.aligned.m8n8.x2.shared.b16 {%0,%1}, [%2];"
                 : "=r"(r[0]), "=r"(r[1]) : "r"(addr));
}
__device__ __forceinline__ void mma16816(float* d, const uint32_t* a, const uint32_t* b) {
    asm volatile("mma.sync.aligned.m16n8k16.row.col.f32.f16.f16.f32 "
                 "{%0,%1,%2,%3}, {%4,%5,%6,%7}, {%8,%9}, {%0,%1,%2,%3};"
                 : "+f"(d[0]), "+f"(d[1]), "+f"(d[2]), "+f"(d[3])
                 : "r"(a[0]), "r"(a[1]), "r"(a[2]), "r"(a[3]), "r"(b[0]), "r"(b[1]));
}

// SW128-style swizzle for 128-byte fp16 rows
__device__ __forceinline__ uint32_t tile_addr(uint32_t base, int row, int kbyte) {
    uint32_t off = row * 128 + kbyte;
    return base + (off ^ ((off >> 3) & 0x70));
}

// ---------------------------------------------------------------------------
// GEMM1 smem: 3 stages x (A32 64x64 fp32 = 16KB, B 128x64 fp16 = 16KB) = 32KB
// GEMM2 smem: 3 stages x (A16 64x64 fp16 = 8KB,  B 128x64 fp16 = 16KB) = 24KB
// ---------------------------------------------------------------------------
#define OFF_A32    0
#define OFF_B1     16384
#define BUF1       32768
#define SMEM1      (3 * BUF1)            // 98304; 2 CTAs/SM -> 192KB

#define OFF_A      0
#define OFF_B      8192
#define BUF_B      24576
#define NSTAGE     3
#define SMEM2      (NSTAGE * BUF_B)      // 73728

// Fill one ROWS x 64-col fp16 tile (SW128 swizzled), 256 threads.
template<int ROWS>
__device__ __forceinline__ void fill_tile(uint32_t sbase, const __half* __restrict__ gsrc,
                                          int row0, int stride, int k0) {
    const int tid = threadIdx.x;
    #pragma unroll
    for (int t = 0; t < ROWS / 32; t++) {
        const int q = tid + t * 256;
        const int r = q >> 3;
        const int c16 = q & 7;
        uint32_t off = r * 128 + c16 * 16;
        uint32_t sw = off ^ ((off >> 3) & 0x70);
        const void* gp = gsrc + (size_t)(row0 + r) * stride + k0 + c16 * 8;
        CP16(sbase + sw, gp);
    }
}

// Fill one 64x64 fp32 A tile (256B rows, 32B-granule XOR swizzle), 256 threads.
// k0 in float units.
__device__ __forceinline__ void fill_a32(uint32_t sbase, const float* __restrict__ src,
                                         int row0, int k0) {
    const int tid = threadIdx.x;
    #pragma unroll
    for (int t = 0; t < 4; t++) {
        const int q = tid + t * 256;          // 0..1023 16B chunks
        const int r = q >> 4;                 // 0..63
        const int c16 = q & 15;               // 16B chunk within 256B row
        uint32_t off = r * 256 + c16 * 16;
        uint32_t sw = off ^ ((uint32_t)(r & 7) << 5);
        const void* gp = src + (size_t)(row0 + r) * NN + k0 + c16 * 4;
        CP16(sbase + sw, gp);
    }
}

// ---------------------------------------------------------------------------
// Preprocessing: weights only (fp32 -> fp16, transposed)
//   blocks [0, 8192)     : W_rel|W_root -> g_w1
//   blocks [8192, 12288) : W_dec -> g_wd
// ---------------------------------------------------------------------------
__global__ __launch_bounds__(256) void conv_pre_kernel(
    const float* __restrict__ W_rel, const float* __restrict__ W_root,
    const float* __restrict__ W_dec)
{
    const int bid = blockIdx.x;
    if (bid < 8192) {
        const int idx = bid * 256 + threadIdx.x;             // n*4096 + k, n<512
        const int n = idx >> 12, k = idx & 4095;
        float v = 0.f;
        if (n < OC)          v = W_rel[k * OC + n];
        else if (n < 2 * OC) v = W_root[k * OC + (n - OC)];
        g_w1[idx] = __float2half(v);
    } else {
        const int idx = (bid - 8192) * 256 + threadIdx.x;    // n*256 + k
        const int n = idx >> 8, k = idx & 255;
        float v = (k < OC) ? W_dec[(size_t)k * NN + n] : 0.f;
        g_wd[idx] = __float2half(v);
    }
}

// relu(z) -> fp16, 8 elems/thread; only cols < 208 consumed by gemm2.
__global__ __launch_bounds__(256) void conv_z_kernel() {
    const int idx = blockIdx.x * 256 + threadIdx.x;
    const int m = idx >> 5;
    const int kk = (idx & 31) * 8;
    if (kk >= 208) return;
    __half2 h[4];
    if (kk < OC) {
        const float4 v0 = *reinterpret_cast<const float4*>(&g_z[m * OC + kk]);
        const float4 v1 = *reinterpret_cast<const float4*>(&g_z[m * OC + kk + 4]);
        h[0] = __half2(__float2half(fmaxf(v0.x, 0.f)), __float2half(fmaxf(v0.y, 0.f)));
        h[1] = __half2(__float2half(fmaxf(v0.z, 0.f)), __float2half(fmaxf(v0.w, 0.f)));
        h[2] = __half2(__float2half(fmaxf(v1.x, 0.f)), __float2half(fmaxf(v1.y, 0.f)));
        h[3] = __half2(__float2half(fmaxf(v1.z, 0.f)), __float2half(fmaxf(v1.w, 0.f)));
    } else {
        #pragma unroll
        for (int t = 0; t < 4; t++) h[t] = __half2(__float2half(0.f), __float2half(0.f));
    }
    #pragma unroll
    for (int t = 0; t < 4; t++)
        *reinterpret_cast<__half2*>(g_zh + m * KPAD + kk + 2 * t) = h[t];
}

// ---------------------------------------------------------------------------
// Edge scatter: g_z[dst] += g_h[src] * w
// ---------------------------------------------------------------------------
__global__ __launch_bounds__(256) void scatter_kernel(const int* __restrict__ ei,
                                                      const float* __restrict__ ew) {
    const int warp = (blockIdx.x * 256 + threadIdx.x) >> 5;
    const int lane = threadIdx.x & 31;
    if (warp >= EE) return;
    const int src = ei[warp];
    const int dst = ei[EE + warp];
    const float w = ew[warp];
    const float4* hs = reinterpret_cast<const float4*>(&g_h[src * OC]);
    float4* zd = reinterpret_cast<float4*>(&g_z[dst * OC]);
    #pragma unroll 2
    for (int c = lane; c < OC / 4; c += 32) {
        const float4 v = __ldg(hs + c);
        asm volatile("red.global.add.v4.f32 [%0], {%1, %2, %3, %4};"
                     :: "l"(zd + c), "f"(v.x * w), "f"(v.y * w), "f"(v.z * w), "f"(v.w * w)
                     : "memory");
    }
}

// ---------------------------------------------------------------------------
// GEMM1 mainloop: A staged as fp32 via cp.async, converted to fp16 in
// registers at fragment build (same RTE rounding as the old conv kernel).
// 64x128 CTA tile, BK=64, 8 warps (2x4), warp tile 32x32.
// ---------------------------------------------------------------------------
template<int NITER>
__device__ __forceinline__ void mma_mainloop_a32(float acc[2][4][4], uint32_t sb,
    const float* __restrict__ A32, int arow0,
    const __half* __restrict__ B, int brow0, int bstride)
{
    const int wid = threadIdx.x >> 5;
    const int lane = threadIdx.x & 31;
    const int wrbase = (wid >> 2) * 32;
    const int wcbase = (wid & 3) * 32;

    const int a_r  = wrbase + (lane >> 2);    // fp32 tile row (frag group)
    const int a_c2 = (lane & 3) * 2;          // fp32 col pair base within k8
    const uint32_t a_swz = (uint32_t)(lane & 31) >> 2 << 5;  // (lane>>2)<<5 granule XOR
    const int b_row = wcbase + (lane & 7);
    const int b_kb  = ((lane >> 3) & 1) * 16;

    fill_a32(sb + 0 * BUF1 + OFF_A32, A32, arow0, 0);
    fill_tile<128>(sb + 0 * BUF1 + OFF_B1, B, brow0, bstride, 0);
    CP_COMMIT();
    fill_a32(sb + 1 * BUF1 + OFF_A32, A32, arow0, 64);
    fill_tile<128>(sb + 1 * BUF1 + OFF_B1, B, brow0, bstride, 64);
    CP_COMMIT();

    int st = 0, fill_st = 2;
    #pragma unroll 1
    for (int iter = 0; iter < NITER; ++iter) {
        CP_WAIT(1);            // stage `st` complete (exactly 2 groups pending at entry)
        __syncthreads();       // all warps done reading the stage `fill_st` overwrites

        if (iter + 2 < NITER) {
            fill_a32(sb + fill_st * BUF1 + OFF_A32, A32, arow0, (iter + 2) * 64);
            fill_tile<128>(sb + fill_st * BUF1 + OFF_B1, B, brow0, bstride, (iter + 2) * 64);
        }
        CP_COMMIT();           // always commit (possibly empty) to keep the count exact

        const uint32_t tA = sb + st * BUF1 + OFF_A32;
        const uint32_t tB = sb + st * BUF1 + OFF_B1;

        #pragma unroll
        for (int ks = 0; ks < 4; ks++) {
            uint32_t a[2][4], b[4][2];
            #pragma unroll
            for (int mi = 0; mi < 2; mi++)
                #pragma unroll
                for (int m = 0; m < 4; m++) {
                    const int row = a_r + mi * 16 + (m & 1) * 8;     // row&7 == lane>>2
                    const int col = ks * 16 + (m >> 1) * 8 + a_c2;
                    const uint32_t byte = (uint32_t)row * 256 + (uint32_t)col * 4;
                    const uint32_t addr = tA + (byte ^ a_swz);
                    float vx, vy;
                    asm volatile("ld.shared.v2.f32 {%0,%1}, [%2];"
                                 : "=f"(vx), "=f"(vy) : "r"(addr));
                    const __half2 hh = __floats2half2_rn(vx, vy);
                    a[mi][m] = *reinterpret_cast<const uint32_t*>(&hh);
                }
            #pragma unroll
            for (int ni = 0; ni < 4; ni++)
                ldsm_x2(b[ni], tile_addr(tB, b_row + ni * 8, ks * 32 + b_kb));
            #pragma unroll
            for (int mi = 0; mi < 2; mi++)
                #pragma unroll
                for (int ni = 0; ni < 4; ni++)
                    mma16816(acc[mi][ni], a[mi], b[ni]);
        }
        st = (st == 2) ? 0 : st + 1;
        fill_st = (fill_st == 2) ? 0 : fill_st + 1;
    }
}

// ---------------------------------------------------------------------------
// GEMM2 mainloop (R8 structure): A fp16 via cp.async, ldmatrix both sides.
// ---------------------------------------------------------------------------
template<int NITER, int LAST_KS>
__device__ __forceinline__ void mma_mainloop(float acc[2][4][4], uint32_t sb,
    const __half* A, int arow0, int astride,
    const __half* B, int brow0, int bstride)
{
    const int wid = threadIdx.x >> 5;
    const int lane = threadIdx.x & 31;
    const int wrbase = (wid >> 2) * 32;
    const int wcbase = (wid & 3) * 32;

    const int a_row = wrbase + (lane & 15);
    const int a_kb  = (lane >> 4) * 16;
    const int b_row = wcbase + (lane & 7);
    const int b_kb  = ((lane >> 3) & 1) * 16;

    fill_tile<64>(sb + 0 * BUF_B + OFF_A, A, arow0, astride, 0);
    fill_tile<128>(sb + 0 * BUF_B + OFF_B, B, brow0, bstride, 0);
    CP_COMMIT();
    fill_tile<64>(sb + 1 * BUF_B + OFF_A, A, arow0, astride, 64);
    fill_tile<128>(sb + 1 * BUF_B + OFF_B, B, brow0, bstride, 64);
    CP_COMMIT();

    int st = 0, fill_st = 2;
    #pragma unroll 1
    for (int iter = 0; iter < NITER; ++iter) {
        CP_WAIT(1);
        __syncthreads();

        if (iter + 2 < NITER) {
            fill_tile<64>(sb + fill_st * BUF_B + OFF_A, A, arow0, astride, (iter + 2) * 64);
            fill_tile<128>(sb + fill_st * BUF_B + OFF_B, B, brow0, bstride, (iter + 2) * 64);
        }
        CP_COMMIT();

        const uint32_t tA = sb + st * BUF_B + OFF_A;
        const uint32_t tB = sb + st * BUF_B + OFF_B;
        const int nks = (iter == NITER - 1) ? LAST_KS : 4;

        #pragma unroll
        for (int ks = 0; ks < 4; ks++) {
            if (ks >= nks) break;
            uint32_t a[2][4], b[4][2];
            #pragma unroll
            for (int mi = 0; mi < 2; mi++)
                ldsm_x4(a[mi], tile_addr(tA, a_row + mi * 16, ks * 32 + a_kb));
            #pragma unroll
            for (int ni = 0; ni < 4; ni++)
                ldsm_x2(b[ni], tile_addr(tB, b_row + ni * 8, ks * 32 + b_kb));
            #pragma unroll
            for (int mi = 0; mi < 2; mi++)
                #pragma unroll
                for (int ni = 0; ni < 4; ni++)
                    mma16816(acc[mi][ni], a[mi], b[ni]);
        }
        st = (st == NSTAGE - 1) ? 0 : st + 1;
        fill_st = (fill_st == NSTAGE - 1) ? 0 : fill_st + 1;
    }
}

// ---------------------------------------------------------------------------
// GEMM1: [g_h | g_z] (4096 x 400) = x @ [W_rel | W_root]    grid (4, 64)
// A read directly from fp32 x (converted in-register at frag build).
// ---------------------------------------------------------------------------
__global__ __launch_bounds__(256, 2) void gemm1_mma(const float* __restrict__ x,
                                                    const float* __restrict__ b_rel) {
    extern __shared__ __align__(1024) char smem[];
    const uint32_t sb = smem_u32(smem);
    const int rowBase = blockIdx.y * 64;
    const int colBase = blockIdx.x * 128;

    float acc[2][4][4];
    #pragma unroll
    for (int i = 0; i < 2; i++)
        #pragma unroll
        for (int j = 0; j < 4; j++)
            #pragma unroll
            for (int t = 0; t < 4; t++) acc[i][j][t] = 0.f;

    mma_mainloop_a32<NN / 64>(acc, sb, x, rowBase, g_w1, colBase, NN);

    const int wid = threadIdx.x >> 5, lane = threadIdx.x & 31;
    const int wrbase = (wid >> 2) * 32, wcbase = (wid & 3) * 32;
    #pragma unroll
    for (int mi = 0; mi < 2; mi++) {
        #pragma unroll
        for (int ni = 0; ni < 4; ni++) {
            const int r0 = rowBase + wrbase + mi * 16 + (lane >> 2);
            const int gc = colBase + wcbase + ni * 8 + (lane & 3) * 2;
            #pragma unroll
            for (int h = 0; h < 2; h++) {
                const int r = r0 + h * 8;
                const float v0 = acc[mi][ni][h * 2 + 0];
                const float v1 = acc[mi][ni][h * 2 + 1];
                if (gc < OC) {
                    g_h[r * OC + gc] = v0;
                    g_h[r * OC + gc + 1] = v1;
                } else if (gc < 2 * OC) {
                    const int c = gc - OC;
                    g_z[r * OC + c] = v0 + __ldg(&b_rel[c]);
                    if (c + 1 < OC) g_z[r * OC + c + 1] = v1 + __ldg(&b_rel[c + 1]);
                }
            }
        }
    }
}

// ---------------------------------------------------------------------------
// GEMM2: out (4096 x 4096) = relu(z) @ W_dec + b_dec    grid (32, 64)
// Effective K = 208 (13 k16-steps): niter=4, last iteration 1 step.
// ---------------------------------------------------------------------------
__global__ __launch_bounds__(256, 2) void gemm2_mma(const float* __restrict__ b_dec,
                                                    float* __restrict__ out) {
    extern __shared__ __align__(1024) char smem[];
    const uint32_t sb = smem_u32(smem);
    const int rowBase = blockIdx.y * 64;
    const int colBase = blockIdx.x * 128;

    float acc[2][4][4];
    #pragma unroll
    for (int i = 0; i < 2; i++)
        #pragma unroll
        for (int j = 0; j < 4; j++)
            #pragma unroll
            for (int t = 0; t < 4; t++) acc[i][j][t] = 0.f;

    mma_mainloop<4, 1>(acc, sb, g_zh, rowBase, KPAD, g_wd, colBase, KPAD);

    const int wid = threadIdx.x >> 5, lane = threadIdx.x & 31;
    const int wrbase = (wid >> 2) * 32, wcbase = (wid & 3) * 32;
    #pragma unroll
    for (int mi = 0; mi < 2; mi++) {
        #pragma unroll
        for (int ni = 0; ni < 4; ni++) {
            const int r0 = rowBase + wrbase + mi * 16 + (lane >> 2);
            const int gc = colBase + wcbase + ni * 8 + (lane & 3) * 2;
            const float b0 = __ldg(&b_dec[gc]);
            const float b1 = __ldg(&b_dec[gc + 1]);
            #pragma unroll
            for (int h = 0; h < 2; h++) {
                const int r = r0 + h * 8;
                float2 o;
                o.x = acc[mi][ni][h * 2 + 0] + b0;
                o.y = acc[mi][ni][h * 2 + 1] + b1;
                *reinterpret_cast<float2*>(&out[(size_t)r * NN + gc]) = o;
            }
        }
    }
}

// ---------------------------------------------------------------------------
// Launch.  Inputs: x, edge_index, edge_weight, W_rel, b_rel, W_root, W_dec, b_dec
// ---------------------------------------------------------------------------
extern "C" void kernel_launch(void* const* d_in, const int* in_sizes, int n_in,
                              void* d_out, int out_size) {
    const float* x      = (const float*)d_in[0];
    const int*   ei     = (const int*)  d_in[1];
    const float* ew     = (const float*)d_in[2];
    const float* W_rel  = (const float*)d_in[3];
    const float* b_rel  = (const float*)d_in[4];
    const float* W_root = (const float*)d_in[5];
    const float* W_dec  = (const float*)d_in[6];
    const float* b_dec  = (const float*)d_in[7];
    float* out = (float*)d_out;

    cudaFuncSetAttribute(gemm1_mma, cudaFuncAttributeMaxDynamicSharedMemorySize, SMEM1);
    cudaFuncSetAttribute(gemm2_mma, cudaFuncAttributeMaxDynamicSharedMemorySize, SMEM2);

    conv_pre_kernel<<<12288, 256>>>(W_rel, W_root, W_dec);

    gemm1_mma<<<dim3(4, 64), 256, SMEM1>>>(x, b_rel);
    scatter_kernel<<<8192, 256>>>(ei, ew);
    conv_z_kernel<<<512, 256>>>();
    gemm2_mma<<<dim3(32, 64), 256, SMEM2>>>(b_dec, out);
}